// round 15
// baseline (speedup 1.0000x reference)
#include <cuda_runtime.h>
#include <cuda_bf16.h>
#include <math.h>
#include <float.h>
#include <stdint.h>

#define NB 8
#define NP 1024
#define KNN 20
#define HL3 448              // hi width of the unified feature buffer
#define HL3LD 896            // [hi(448) | lo(448)]

// ---------------- scratch (device globals; no allocation allowed) ----------------
__device__ __align__(16) float g_dist[NB * NP * NP];            // 32 MB
__device__ __align__(16) int   g_idx[NB * NP * KNN];
__device__ __align__(16) float g_xx[4][NB * NP];                // per-layer squared norms
__device__ __align__(16) float g_ab[NB * NP * 1024];
__device__ __align__(16) float g_hf[NB * NP * 512];
__device__ __align__(16) float g_pooled[NB * 512];
__device__ __align__(16) float g_bias4[4 * 512];
__device__ __align__(16) __nv_bfloat16 g_hl0[NB * NP * 64];      // layer0 [hi(32)|lo(32)]
__device__ __align__(16) __nv_bfloat16 g_hl3[NB * NP * HL3LD];   // unified features [hi|lo]
__device__ __align__(16) __nv_bfloat16 g_whl4[4][1024 * HL3LD];  // per-layer folded weights [hi|lo]

// =================== helpers ===================
__device__ __forceinline__ uint32_t smem_u32(const void* p) {
    uint32_t a;
    asm("{ .reg .u64 t; cvta.to.shared.u64 t, %1; cvt.u32.u64 %0, t; }" : "=r"(a) : "l"(p));
    return a;
}
__device__ __forceinline__ void cpa16(uint32_t s, const void* g) {
    asm volatile("cp.async.cg.shared.global [%0], [%1], 16;" :: "r"(s), "l"(g));
}
#define CP_COMMIT() asm volatile("cp.async.commit_group;")
#define CP_WAIT2()  asm volatile("cp.async.wait_group 2;")
#define CP_WAIT1()  asm volatile("cp.async.wait_group 1;")
#define CP_WAIT0()  asm volatile("cp.async.wait_group 0;")

__device__ __forceinline__ void ldsm_x4(uint32_t* r, uint32_t addr) {
    asm volatile("ldmatrix.sync.aligned.m8n8.x4.shared.b16 {%0,%1,%2,%3}, [%4];"
        : "=r"(r[0]), "=r"(r[1]), "=r"(r[2]), "=r"(r[3]) : "r"(addr));
}

// =================== layer-0 feature split (from x) + norms ===================
__global__ void split_kernel(const float* __restrict__ src, int ld, int C,
                             __nv_bfloat16* __restrict__ hl, int Cp,
                             float* __restrict__ xxout)
{
    __shared__ float red[4];
    int r = blockIdx.x;
    const float* p = src + (long long)r * ld;
    __nv_bfloat16* o = hl + (long long)r * 2 * Cp;
    __nv_bfloat16 z = __float2bfloat16(0.f);
    float ss = 0.f;
    for (int k = threadIdx.x; k < 2 * Cp; k += blockDim.x) {
        bool isHi = k < Cp;
        int c = isHi ? k : k - Cp;
        __nv_bfloat16 vv = z;
        if (c < C) {
            float x = p[c];
            if (isHi) ss += x * x;
            __nv_bfloat16 hi = __float2bfloat16(x);
            vv = isHi ? hi : __float2bfloat16(x - __bfloat162float(hi));
        }
        o[k] = vv;
    }
    int lane = threadIdx.x & 31, w = threadIdx.x >> 5;
    #pragma unroll
    for (int of = 16; of; of >>= 1) ss += __shfl_xor_sync(0xffffffffu, ss, of);
    if (!lane) red[w] = ss;
    __syncthreads();
    if (threadIdx.x == 0) {
        float t = 0.f;
        for (int i = 0; i < (blockDim.x + 31) / 32; i++) t += red[i];
        xxout[r] = t;
    }
}

// =================== fold BN into weights -> [hi(Cp) | lo(Cp)] ===================
__global__ void wfoldsplit_kernel(const float* __restrict__ W, const float* __restrict__ g,
                                  const float* __restrict__ be, const float* __restrict__ m,
                                  const float* __restrict__ v, int O, int C, int Cp,
                                  __nv_bfloat16* __restrict__ whl,
                                  float* __restrict__ bias)
{
    int r = blockIdx.x;                 // 0 .. 2O-1
    bool isA = r < O;
    int o = isA ? r : r - O;
    float s = g[o] * rsqrtf(v[o] + 1e-5f);
    if (threadIdx.x == 0 && isA) bias[o] = be[o] - s * m[o];
    __nv_bfloat16* out = whl + (long long)r * 2 * Cp;
    __nv_bfloat16 z = __float2bfloat16(0.f);
    for (int k = threadIdx.x; k < 2 * Cp; k += blockDim.x) {
        bool isHi = k < Cp;
        int c = isHi ? k : k - Cp;
        __nv_bfloat16 vv = z;
        if (c < C) {
            float wc = W[o * 2 * C + c];
            float wd = W[o * 2 * C + C + c];
            float val = isA ? s * (wd - wc) : s * wc;
            __nv_bfloat16 hi = __float2bfloat16(val);
            vv = isHi ? hi : __float2bfloat16(val - __bfloat162float(hi));
        }
        out[k] = vv;
    }
}

// =================== mma.sync bf16 GEMM over virtual K = 3*Cp ===================
// A virtual [hi|lo|hi], B virtual [hi|hi|lo]; per-operand (ld, loOff) so the
// operands can live in slice views of hl3 (loOff=448) or packed weights (loOff=Cp).
#define SSTR 56
#define ASZ  (128 * SSTR)
#define NSTAGE 3
#define GEMM_SMEM (NSTAGE * ASZ * 2 * 2)
#define TSTR 132            // transpose staging stride (floats)

__device__ __forceinline__ void mma16816(float* c, const uint32_t* a, const uint32_t* b)
{
    asm volatile(
        "mma.sync.aligned.m16n8k16.row.col.f32.bf16.bf16.f32 "
        "{%0,%1,%2,%3}, {%4,%5,%6,%7}, {%8,%9}, {%0,%1,%2,%3};"
        : "+f"(c[0]), "+f"(c[1]), "+f"(c[2]), "+f"(c[3])
        : "r"(a[0]), "r"(a[1]), "r"(a[2]), "r"(a[3]), "r"(b[0]), "r"(b[1]));
}

__device__ __forceinline__ int koff_a(int ka, int Cp, int lo) {
    return (ka < Cp) ? ka : ((ka < 2 * Cp) ? lo + (ka - Cp) : ka - 2 * Cp);
}
__device__ __forceinline__ int koff_b(int ka, int Cp, int lo) {
    return (ka < Cp) ? ka : ((ka < 2 * Cp) ? ka - Cp : lo + (ka - 2 * Cp));
}

// mode 0: SYMMETRIC dist (gridDim.x=36, lower-triangle tiles; mirrors off-diag)
// mode 1: weight projection (gridDim x=2O/128, y=NP/128)
__global__ __launch_bounds__(256, 2) void mma_gemm_kernel(
    const __nv_bfloat16* __restrict__ A,
    const __nv_bfloat16* __restrict__ Bm,
    int Cp, int ldA, int loA, int ldB, int loB,
    long long bsA, long long bsB,
    const float* __restrict__ xx, int mode,
    float* __restrict__ out, int ldo)
{
    extern __shared__ __align__(16) __nv_bfloat16 sm[];
    __nv_bfloat16* As = sm;
    __nv_bfloat16* Bs = sm + NSTAGE * ASZ;

    int b = blockIdx.z;
    int row0, col0;
    bool mirror = false;
    if (mode == 0) {
        int t = blockIdx.x;
        int by = 0;
        while (t >= by + 1) { t -= by + 1; by++; }
        row0 = by * 128;
        col0 = t * 128;
        mirror = (t != by);
    } else {
        row0 = blockIdx.y * 128;
        col0 = blockIdx.x * 128;
    }

    int tid = threadIdx.x;
    int wid = tid >> 5, lane = tid & 31;
    int wm = (wid >> 2) * 64;
    int wn = (wid & 3) * 32;

    int nk = (3 * Cp) >> 5;

    const __nv_bfloat16* Ab = A + (long long)b * bsA;
    const __nv_bfloat16* Bb = Bm + (long long)b * bsB;

    int lr = tid >> 1;
    int lc = (tid & 1) * 16;

    uint32_t sAraw = smem_u32(As);
    uint32_t sBraw = smem_u32(Bs);
    uint32_t sA0 = sAraw + (uint32_t)(lr * SSTR + lc) * 2;
    uint32_t sB0 = sBraw + (uint32_t)(lr * SSTR + lc) * 2;
    const __nv_bfloat16* gA = Ab + (long long)(row0 + lr) * ldA + lc;
    const __nv_bfloat16* gB = Bb + (long long)(col0 + lr) * ldB + lc;

    uint32_t a_off = (uint32_t)((wm + (lane & 15)) * SSTR + (lane >> 4) * 8);
    uint32_t b_off = (uint32_t)((wn + (lane & 7) + ((lane >> 4) & 1) * 8) * SSTR
                                + ((lane >> 3) & 1) * 8);

    #pragma unroll
    for (int s = 0; s < NSTAGE - 1; s++) {
        if (s < nk) {
            int ka = s * 32;
            int oa = koff_a(ka, Cp, loA);
            int ob = koff_b(ka, Cp, loB);
            uint32_t da = sA0 + (uint32_t)(s * ASZ) * 2;
            uint32_t db = sB0 + (uint32_t)(s * ASZ) * 2;
            cpa16(da, gA + oa); cpa16(da + 16, gA + oa + 8);
            cpa16(db, gB + ob); cpa16(db + 16, gB + ob + 8);
            CP_COMMIT();
        }
    }

    float acc[4][4][4] = {};

    for (int kc = 0; kc < nk; kc++) {
        int cur = kc % NSTAGE;
        if (kc + 2 < nk) {
            int nxt = (kc + 2) % NSTAGE;
            int ka = (kc + 2) * 32;
            int oa = koff_a(ka, Cp, loA);
            int ob = koff_b(ka, Cp, loB);
            uint32_t da = sA0 + (uint32_t)(nxt * ASZ) * 2;
            uint32_t db = sB0 + (uint32_t)(nxt * ASZ) * 2;
            cpa16(da, gA + oa); cpa16(da + 16, gA + oa + 8);
            cpa16(db, gB + ob); cpa16(db + 16, gB + ob + 8);
            CP_COMMIT();
            CP_WAIT2();
        } else if (kc + 1 < nk) {
            CP_WAIT1();
        } else {
            CP_WAIT0();
        }
        __syncthreads();

        uint32_t aCur = sAraw + (uint32_t)(cur * ASZ) * 2 + a_off * 2;
        uint32_t bCur = sBraw + (uint32_t)(cur * ASZ) * 2 + b_off * 2;
        #pragma unroll
        for (int kk = 0; kk < 32; kk += 16) {
            uint32_t af[4][4], bq[2][4];
            #pragma unroll
            for (int mf = 0; mf < 4; mf++)
                ldsm_x4(af[mf], aCur + (uint32_t)(mf * 16 * SSTR + kk) * 2);
            #pragma unroll
            for (int nq = 0; nq < 2; nq++)
                ldsm_x4(bq[nq], bCur + (uint32_t)(nq * 16 * SSTR + kk) * 2);
            #pragma unroll
            for (int mf = 0; mf < 4; mf++)
                #pragma unroll
                for (int nf = 0; nf < 4; nf++)
                    mma16816(acc[mf][nf], af[mf], &bq[nf >> 1][(nf & 1) * 2]);
        }
        __syncthreads();
    }

    int ar = lane >> 2, ac = (lane & 3) * 2;
    if (mode == 0) {
        const float* xxb = xx + b * NP;
        float* st = (float*)sm;
        #pragma unroll
        for (int mf = 0; mf < 4; mf++) {
            int r0g = row0 + wm + mf * 16 + ar;
            float xi0 = xxb[r0g], xi1 = xxb[r0g + 8];
            #pragma unroll
            for (int nf = 0; nf < 4; nf++) {
                int cg = col0 + wn + nf * 8 + ac;
                float* acc4 = acc[mf][nf];
                float xj0 = xxb[cg], xj1 = xxb[cg + 1];
                float2 v0, v1;
                v0.x = 2.f * acc4[0] - xi0 - xj0;
                v0.y = 2.f * acc4[1] - xi0 - xj1;
                v1.x = 2.f * acc4[2] - xi1 - xj0;
                v1.y = 2.f * acc4[3] - xi1 - xj1;
                *(float2*)(out + ((long long)b * NP + r0g) * ldo + cg) = v0;
                *(float2*)(out + ((long long)b * NP + r0g + 8) * ldo + cg) = v1;
                if (mirror) {
                    int lr0 = wm + mf * 16 + ar;
                    int lc0 = wn + nf * 8 + ac;
                    st[(lc0 + 0) * TSTR + lr0]     = v0.x;
                    st[(lc0 + 1) * TSTR + lr0]     = v0.y;
                    st[(lc0 + 0) * TSTR + lr0 + 8] = v1.x;
                    st[(lc0 + 1) * TSTR + lr0 + 8] = v1.y;
                }
            }
        }
        if (mirror) {
            __syncthreads();
            for (int e = tid; e < 128 * 32; e += 256) {
                int tr = e >> 5;
                int tc = (e & 31) * 4;
                float4 val = *(float4*)&st[tr * TSTR + tc];
                *(float4*)(out + ((long long)b * NP + col0 + tr) * ldo + row0 + tc) = val;
            }
        }
    } else {
        #pragma unroll
        for (int mf = 0; mf < 4; mf++) {
            int r0g = row0 + wm + mf * 16 + ar;
            #pragma unroll
            for (int nf = 0; nf < 4; nf++) {
                int cg = col0 + wn + nf * 8 + ac;
                float* acc4 = acc[mf][nf];
                float2 v0, v1;
                v0.x = acc4[0]; v0.y = acc4[1];
                v1.x = acc4[2]; v1.y = acc4[3];
                *(float2*)(out + ((long long)b * NP + r0g) * ldo + cg) = v0;
                *(float2*)(out + ((long long)b * NP + r0g + 8) * ldo + cg) = v1;
            }
        }
    }
}

// =================== top-20: sorted top-4 queues + verify ===================
__global__ void topk_kernel(const float* __restrict__ dist, int* __restrict__ idx)
{
    int row = blockIdx.x * (blockDim.x >> 5) + (threadIdx.x >> 5);
    int lane = threadIdx.x & 31;
    if (row >= NB * NP) return;
    const float* d = dist + (size_t)row * NP;
    float v[32];
    #pragma unroll
    for (int s = 0; s < 32; s++) v[s] = d[s * 32 + lane];

    float m0 = -FLT_MAX, m1 = -FLT_MAX, m2 = -FLT_MAX, m3 = -FLT_MAX;
    int q0 = 0, q1 = 0, q2 = 0, q3 = 0;
    #pragma unroll
    for (int s = 0; s < 32; s++) {
        float x = v[s];
        if (x > m3) {
            if (x > m0)      { m3 = m2; q3 = q2; m2 = m1; q2 = q1; m1 = m0; q1 = q0; m0 = x; q0 = s; }
            else if (x > m1) { m3 = m2; q3 = q2; m2 = m1; q2 = q1; m1 = x;  q1 = s; }
            else if (x > m2) { m3 = m2; q3 = q2; m2 = x;  q2 = s; }
            else             { m3 = x;  q3 = s; }
        }
    }

    float thresh = 0.f;
    #pragma unroll
    for (int t = 0; t < KNN; t++) {
        float best = m0;
        #pragma unroll
        for (int off = 16; off; off >>= 1)
            best = fmaxf(best, __shfl_xor_sync(0xffffffffu, best, off));
        unsigned mask = __ballot_sync(0xffffffffu, m0 == best);
        int wl = __ffs(mask) - 1;
        int wq = __shfl_sync(0xffffffffu, q0, wl);
        if (lane == 0) idx[row * KNN + t] = wq * 32 + wl;
        if (lane == wl) { m0 = m1; q0 = q1; m1 = m2; q1 = q2; m2 = m3; q2 = q3; m3 = -FLT_MAX; }
        thresh = best;
    }

    int cnt = 0;
    #pragma unroll
    for (int s = 0; s < 32; s++) cnt += (v[s] > thresh) ? 1 : 0;
    cnt = __reduce_add_sync(0xffffffffu, cnt);
    if (cnt == 19) return;

    for (int t = 0; t < KNN; t++) {
        float best = -FLT_MAX; int bs = 0;
        #pragma unroll
        for (int s = 0; s < 32; s++)
            if (v[s] > best) { best = v[s]; bs = s; }
        int bj = bs * 32 + lane;
        #pragma unroll
        for (int off = 16; off; off >>= 1) {
            float ov = __shfl_xor_sync(0xffffffffu, best, off);
            int oj = __shfl_xor_sync(0xffffffffu, bj, off);
            if (ov > best || (ov == best && oj < bj)) { best = ov; bj = oj; }
        }
        if (lane == 0) idx[row * KNN + t] = bj;
        if ((bj & 31) == lane) {
            int ks = bj >> 5;
            #pragma unroll
            for (int s = 0; s < 32; s++)
                if (s == ks) v[s] = -FLT_MAX;
        }
    }
}

// =================== edge aggregate, fused with hi/lo split + norms ===================
// outF != null (last layer): write fp32 to outF (ld 512).
// outF == null: write (hi,lo) into hl3 at column coloff, xxn[pt] = sum(val^2),
//               and xx3 set (xx3mode==1) or accumulate (xx3mode==2).
__global__ void aggregate_kernel(const float* __restrict__ ab, int O,
                                 const float* __restrict__ bias,
                                 const int* __restrict__ idx,
                                 float* __restrict__ outF,
                                 __nv_bfloat16* __restrict__ hl3, int coloff,
                                 float* __restrict__ xxn,
                                 float* __restrict__ xx3, int xx3mode)
{
    __shared__ int sj[KNN];
    __shared__ float red[8];
    int bi = blockIdx.x;
    int b = bi >> 10, i = bi & 1023;
    if (threadIdx.x < KNN) sj[threadIdx.x] = idx[bi * KNN + threadIdx.x];
    __syncthreads();
    const float* abb = ab + (size_t)b * NP * 2 * O;
    float ss = 0.f;
    for (int o = threadIdx.x; o < O; o += blockDim.x) {
        float a = abb[(size_t)i * 2 * O + o] + bias[o];
        float acc = 0.f;
        #pragma unroll
        for (int k = 0; k < KNN; k++) {
            float val = a + abb[(size_t)sj[k] * 2 * O + O + o];
            acc += fmaxf(val, 0.2f * val);
        }
        float val = acc * 0.05f;
        if (outF) {
            outF[((size_t)b * NP + i) * 512 + o] = val;
        } else {
            ss += val * val;
            __nv_bfloat16 hi = __float2bfloat16(val);
            __nv_bfloat16 lo = __float2bfloat16(val - __bfloat162float(hi));
            __nv_bfloat16* row = hl3 + (size_t)(b * NP + i) * HL3LD;
            row[coloff + o] = hi;
            row[HL3 + coloff + o] = lo;
        }
    }
    if (!outF) {
        int lane = threadIdx.x & 31, w = threadIdx.x >> 5;
        #pragma unroll
        for (int of = 16; of; of >>= 1) ss += __shfl_xor_sync(0xffffffffu, ss, of);
        if (!lane) red[w] = ss;
        __syncthreads();
        if (threadIdx.x == 0) {
            float t = 0.f;
            int nw = (blockDim.x + 31) >> 5;
            for (int k = 0; k < nw; k++) t += red[k];
            if (xxn) xxn[b * NP + i] = t;
            if (xx3mode == 1) xx3[b * NP + i] = t;
            else if (xx3mode == 2) xx3[b * NP + i] += t;
        }
    }
}

// =================== pooling + final linear ===================
__global__ void pool_kernel(const float* __restrict__ hf, float* __restrict__ pooled)
{
    int b = blockIdx.x;
    int o = blockIdx.y * blockDim.x + threadIdx.x;
    float s = 0.f;
    for (int i = 0; i < NP; i++) s += hf[((size_t)b * NP + i) * 512 + o];
    pooled[b * 512 + o] = s * (1.f / NP);
}

__global__ void final_kernel(const float* __restrict__ pooled, const float* __restrict__ We,
                             float* __restrict__ out)
{
    int b = blockIdx.x, e = threadIdx.x;
    const float* p = pooled + b * 512;
    const float* w = We + e * 512;
    float s = 0.f;
    for (int o = 0; o < 512; o++) s += p[o] * w[o];
    out[b * 256 + e] = s;
}

// =================== host side ===================
struct LayerCfg { int C, Cp, O, hoff; const float *W, *g, *be, *m, *v; };

extern "C" void kernel_launch(void* const* d_in, const int* in_sizes, int n_in,
                              void* d_out, int out_size)
{
    const float* x  = (const float*)d_in[0];
    const float* We = (const float*)d_in[21];

    float *dist, *ab, *hf, *pooled, *bias4, *xxv;
    int* idx;
    __nv_bfloat16 *hl0, *hl3, *whl4;
    cudaGetSymbolAddress((void**)&dist,   g_dist);
    cudaGetSymbolAddress((void**)&idx,    g_idx);
    cudaGetSymbolAddress((void**)&xxv,    g_xx);
    cudaGetSymbolAddress((void**)&ab,     g_ab);
    cudaGetSymbolAddress((void**)&hf,     g_hf);
    cudaGetSymbolAddress((void**)&pooled, g_pooled);
    cudaGetSymbolAddress((void**)&bias4,  g_bias4);
    cudaGetSymbolAddress((void**)&hl0,    g_hl0);
    cudaGetSymbolAddress((void**)&hl3,    g_hl3);
    cudaGetSymbolAddress((void**)&whl4,   g_whl4);

    static cudaStream_t sB = nullptr;
    static cudaEvent_t evRoot, evRdy[4], evB[4];
    static bool attrSet = false;
    if (!sB) {
        cudaStreamCreateWithFlags(&sB, cudaStreamNonBlocking);
        cudaEventCreateWithFlags(&evRoot, cudaEventDisableTiming);
        for (int i = 0; i < 4; i++) {
            cudaEventCreateWithFlags(&evRdy[i], cudaEventDisableTiming);
            cudaEventCreateWithFlags(&evB[i], cudaEventDisableTiming);
        }
    }
    if (!attrSet) {
        cudaFuncSetAttribute(mma_gemm_kernel,
                             cudaFuncAttributeMaxDynamicSharedMemorySize, GEMM_SMEM);
        attrSet = true;
    }

    LayerCfg L[4] = {
        {  3,  32,  64,   0, (const float*)d_in[1],  (const float*)d_in[2],  (const float*)d_in[3],  (const float*)d_in[4],  (const float*)d_in[5]  },
        { 64,  64, 128,   0, (const float*)d_in[6],  (const float*)d_in[7],  (const float*)d_in[8],  (const float*)d_in[9],  (const float*)d_in[10] },
        {128, 128, 256,  64, (const float*)d_in[11], (const float*)d_in[12], (const float*)d_in[13], (const float*)d_in[14], (const float*)d_in[15] },
        {448, 448, 512,   0, (const float*)d_in[16], (const float*)d_in[17], (const float*)d_in[18], (const float*)d_in[19], (const float*)d_in[20] },
    };
    // aggregate i (<3) writes hl3 cols at ooffs[i], feeds xx layer i+1
    int ooffs[3] = {0, 64, 192};

    cudaEventRecord(evRoot, 0);
    cudaStreamWaitEvent(sB, evRoot, 0);

    for (int i = 0; i < 4; i++) {
        wfoldsplit_kernel<<<2 * L[i].O, 128, 0, sB>>>(
            L[i].W, L[i].g, L[i].be, L[i].m, L[i].v, L[i].O, L[i].C, L[i].Cp,
            whl4 + (size_t)i * 1024 * HL3LD, bias4 + i * 512);
    }

    // layer0 feature split from x
    split_kernel<<<NB * NP, 64>>>(x, 3, 3, hl0, 32, xxv + 0 * NB * NP);
    cudaEventRecord(evRdy[0], 0);

    for (int i = 0; i < 4; i++) {
        int Cp = L[i].Cp, O = L[i].O;
        const __nv_bfloat16* Af = (i == 0) ? hl0 : (hl3 + L[i].hoff);
        int ldA = (i == 0) ? 64 : HL3LD;
        int loA = (i == 0) ? 32 : HL3;
        long long bsA = (long long)NP * ldA;
        float* xxi = xxv + (size_t)i * NB * NP;

        // stream B: weight GEMM (waits for features of this layer)
        cudaStreamWaitEvent(sB, evRdy[i], 0);
        dim3 gw((2 * O) / 128, NP / 128, NB);
        mma_gemm_kernel<<<gw, 256, GEMM_SMEM, sB>>>(
            Af, whl4 + (size_t)i * 1024 * HL3LD, Cp,
            ldA, loA, 2 * Cp, Cp,
            bsA, 0, nullptr, 1, ab, 2 * O);
        cudaEventRecord(evB[i], sB);

        // main: symmetric dist GEMM + topk
        dim3 gd(36, 1, NB);
        mma_gemm_kernel<<<gd, 256, GEMM_SMEM>>>(
            Af, Af, Cp, ldA, loA, ldA, loA,
            bsA, bsA, xxi, 0, dist, NP);
        topk_kernel<<<NB * NP / 8, 256>>>(dist, idx);

        // join + fused aggregate
        cudaStreamWaitEvent(0, evB[i], 0);
        int bt = O < 256 ? O : 256;
        if (i < 3) {
            float* xxn = (i < 2) ? (xxv + (size_t)(i + 1) * NB * NP) : nullptr;
            int xx3mode = (i == 0) ? 1 : 2;
            aggregate_kernel<<<NB * NP, bt>>>(ab, O, bias4 + i * 512, idx,
                                              nullptr, hl3, ooffs[i],
                                              xxn, xxv + 3 * NB * NP, xx3mode);
            cudaEventRecord(evRdy[i + 1], 0);
        } else {
            aggregate_kernel<<<NB * NP, bt>>>(ab, O, bias4 + i * 512, idx,
                                              hf, nullptr, 0, nullptr, nullptr, 0);
        }
    }

    pool_kernel<<<dim3(NB, 2), 256>>>(hf, pooled);
    final_kernel<<<NB, 256>>>(pooled, We, (float*)d_out);
}

// round 16
// speedup vs baseline: 1.0565x; 1.0565x over previous
#include <cuda_runtime.h>
#include <cuda_bf16.h>
#include <cuda_fp16.h>
#include <math.h>
#include <float.h>
#include <stdint.h>

#define NB 8
#define NP 1024
#define KNN 20
#define HLMAX 896            // 2*448: [hi|lo] width for the largest layer

// ---------------- scratch (device globals; no allocation allowed) ----------------
__device__ __align__(16) float g_dist[NB * NP * NP];            // 32 MB
__device__ __align__(16) int   g_idx[NB * NP * KNN];
__device__ __align__(16) float g_xx[NB * NP];
__device__ __align__(16) float g_cat[NB * NP * 448];
__device__ __align__(16) __half g_ab[NB * NP * 1024];           // fp16 a/b projections (16 MB)
__device__ __align__(16) float g_hf[NB * NP * 512];
__device__ __align__(16) float g_pooled[NB * 512];
__device__ __align__(16) float g_bias4[4 * 512];
__device__ __align__(16) __nv_bfloat16 g_hl[NB * NP * HLMAX];    // features [hi|lo]
__device__ __align__(16) __nv_bfloat16 g_whl4[4][1024 * HLMAX];  // per-layer folded weights [hi|lo]

// =================== helpers ===================
__device__ __forceinline__ uint32_t smem_u32(const void* p) {
    uint32_t a;
    asm("{ .reg .u64 t; cvta.to.shared.u64 t, %1; cvt.u32.u64 %0, t; }" : "=r"(a) : "l"(p));
    return a;
}
__device__ __forceinline__ void cpa16(uint32_t s, const void* g) {
    asm volatile("cp.async.cg.shared.global [%0], [%1], 16;" :: "r"(s), "l"(g));
}
#define CP_COMMIT() asm volatile("cp.async.commit_group;")
#define CP_WAIT2()  asm volatile("cp.async.wait_group 2;")
#define CP_WAIT1()  asm volatile("cp.async.wait_group 1;")
#define CP_WAIT0()  asm volatile("cp.async.wait_group 0;")

__device__ __forceinline__ void ldsm_x4(uint32_t* r, uint32_t addr) {
    asm volatile("ldmatrix.sync.aligned.m8n8.x4.shared.b16 {%0,%1,%2,%3}, [%4];"
        : "=r"(r[0]), "=r"(r[1]), "=r"(r[2]), "=r"(r[3]) : "r"(addr));
}

// =================== feature split -> [hi(Cp) | lo(Cp)] + fused norms ===================
__global__ void split_kernel(const float* __restrict__ src, int ld, int coff, int C,
                             long long bstride, int rows_per_b,
                             __nv_bfloat16* __restrict__ hl, int Cp,
                             float* __restrict__ xxout)
{
    __shared__ float red[4];
    int r = blockIdx.x;
    int b = r / rows_per_b;
    int ri = r - b * rows_per_b;
    const float* p = src + (long long)b * bstride + (long long)ri * ld + coff;
    __nv_bfloat16* o = hl + (long long)r * 2 * Cp;
    __nv_bfloat16 z = __float2bfloat16(0.f);
    float ss = 0.f;
    for (int k = threadIdx.x; k < 2 * Cp; k += blockDim.x) {
        bool isHi = k < Cp;
        int c = isHi ? k : k - Cp;
        __nv_bfloat16 vv = z;
        if (c < C) {
            float x = p[c];
            if (isHi) ss += x * x;
            __nv_bfloat16 hi = __float2bfloat16(x);
            vv = isHi ? hi : __float2bfloat16(x - __bfloat162float(hi));
        }
        o[k] = vv;
    }
    int lane = threadIdx.x & 31, w = threadIdx.x >> 5;
    #pragma unroll
    for (int of = 16; of; of >>= 1) ss += __shfl_xor_sync(0xffffffffu, ss, of);
    if (!lane) red[w] = ss;
    __syncthreads();
    if (threadIdx.x == 0)
        xxout[r] = red[0] + red[1] + red[2] + red[3];
}

// =================== fold BN into weights -> [hi(Cp) | lo(Cp)] ===================
__global__ void wfoldsplit_kernel(const float* __restrict__ W, const float* __restrict__ g,
                                  const float* __restrict__ be, const float* __restrict__ m,
                                  const float* __restrict__ v, int O, int C, int Cp,
                                  __nv_bfloat16* __restrict__ whl,
                                  float* __restrict__ bias)
{
    int r = blockIdx.x;                 // 0 .. 2O-1
    bool isA = r < O;
    int o = isA ? r : r - O;
    float s = g[o] * rsqrtf(v[o] + 1e-5f);
    if (threadIdx.x == 0 && isA) bias[o] = be[o] - s * m[o];
    __nv_bfloat16* out = whl + (long long)r * 2 * Cp;
    __nv_bfloat16 z = __float2bfloat16(0.f);
    for (int k = threadIdx.x; k < 2 * Cp; k += blockDim.x) {
        bool isHi = k < Cp;
        int c = isHi ? k : k - Cp;
        __nv_bfloat16 vv = z;
        if (c < C) {
            float wc = W[o * 2 * C + c];
            float wd = W[o * 2 * C + C + c];
            float val = isA ? s * (wd - wc) : s * wc;
            __nv_bfloat16 hi = __float2bfloat16(val);
            vv = isHi ? hi : __float2bfloat16(val - __bfloat162float(hi));
        }
        out[k] = vv;
    }
}

// =================== mma.sync bf16 GEMM over virtual K = 3*Cp ===================
// A virtual [hi|lo|hi]; B virtual [hi|hi|lo] => D = hh + lh + hl ≈ fp32 product.
#define SSTR 56
#define ASZ  (128 * SSTR)
#define NSTAGE 3
#define GEMM_SMEM (NSTAGE * ASZ * 2 * 2)
#define TSTR 132            // transpose staging stride (floats)

__device__ __forceinline__ void mma16816(float* c, const uint32_t* a, const uint32_t* b)
{
    asm volatile(
        "mma.sync.aligned.m16n8k16.row.col.f32.bf16.bf16.f32 "
        "{%0,%1,%2,%3}, {%4,%5,%6,%7}, {%8,%9}, {%0,%1,%2,%3};"
        : "+f"(c[0]), "+f"(c[1]), "+f"(c[2]), "+f"(c[3])
        : "r"(a[0]), "r"(a[1]), "r"(a[2]), "r"(a[3]), "r"(b[0]), "r"(b[1]));
}

// mode 0: SYMMETRIC dist (gridDim.x=36 lower-triangle tiles; mirrors off-diag), fp32 out.
// mode 1: weight projection, fp16 out (outH).
__global__ __launch_bounds__(256, 2) void mma_gemm_kernel(
    const __nv_bfloat16* __restrict__ A,
    const __nv_bfloat16* __restrict__ Bm,
    int Cp, long long bsA, long long bsB,
    const float* __restrict__ xx, int mode,
    float* __restrict__ out, __half* __restrict__ outH, int ldo)
{
    extern __shared__ __align__(16) __nv_bfloat16 sm[];
    __nv_bfloat16* As = sm;
    __nv_bfloat16* Bs = sm + NSTAGE * ASZ;

    int b = blockIdx.z;
    int row0, col0;
    bool mirror = false;
    if (mode == 0) {
        int t = blockIdx.x;            // 0..35 -> (bx<=by)
        int by = 0;
        while (t >= by + 1) { t -= by + 1; by++; }
        row0 = by * 128;
        col0 = t * 128;
        mirror = (t != by);
    } else {
        row0 = blockIdx.y * 128;
        col0 = blockIdx.x * 128;
    }

    int tid = threadIdx.x;
    int wid = tid >> 5, lane = tid & 31;
    int wm = (wid >> 2) * 64;
    int wn = (wid & 3) * 32;

    int ld2 = 2 * Cp;
    int nk = (3 * Cp) >> 5;

    const __nv_bfloat16* Ab = A + (long long)b * bsA;
    const __nv_bfloat16* Bb = Bm + (long long)b * bsB;

    int lr = tid >> 1;
    int lc = (tid & 1) * 16;

    uint32_t sAraw = smem_u32(As);
    uint32_t sBraw = smem_u32(Bs);
    uint32_t sA0 = sAraw + (uint32_t)(lr * SSTR + lc) * 2;
    uint32_t sB0 = sBraw + (uint32_t)(lr * SSTR + lc) * 2;
    const __nv_bfloat16* gA = Ab + (long long)(row0 + lr) * ld2 + lc;
    const __nv_bfloat16* gB = Bb + (long long)(col0 + lr) * ld2 + lc;

    uint32_t a_off = (uint32_t)((wm + (lane & 15)) * SSTR + (lane >> 4) * 8);
    uint32_t b_off = (uint32_t)((wn + (lane & 7) + ((lane >> 4) & 1) * 8) * SSTR
                                + ((lane >> 3) & 1) * 8);

    #pragma unroll
    for (int s = 0; s < NSTAGE - 1; s++) {
        if (s < nk) {
            int ka = s * 32;
            int koffA = (ka < 2 * Cp) ? ka : ka - 2 * Cp;
            int koffB = (ka < Cp) ? ka : ka - Cp;
            uint32_t da = sA0 + (uint32_t)(s * ASZ) * 2;
            uint32_t db = sB0 + (uint32_t)(s * ASZ) * 2;
            cpa16(da, gA + koffA); cpa16(da + 16, gA + koffA + 8);
            cpa16(db, gB + koffB); cpa16(db + 16, gB + koffB + 8);
            CP_COMMIT();
        }
    }

    float acc[4][4][4] = {};

    for (int kc = 0; kc < nk; kc++) {
        int cur = kc % NSTAGE;
        if (kc + 2 < nk) {
            int nxt = (kc + 2) % NSTAGE;
            int ka = (kc + 2) * 32;
            int koffA = (ka < 2 * Cp) ? ka : ka - 2 * Cp;
            int koffB = (ka < Cp) ? ka : ka - Cp;
            uint32_t da = sA0 + (uint32_t)(nxt * ASZ) * 2;
            uint32_t db = sB0 + (uint32_t)(nxt * ASZ) * 2;
            cpa16(da, gA + koffA); cpa16(da + 16, gA + koffA + 8);
            cpa16(db, gB + koffB); cpa16(db + 16, gB + koffB + 8);
            CP_COMMIT();
            CP_WAIT2();
        } else if (kc + 1 < nk) {
            CP_WAIT1();
        } else {
            CP_WAIT0();
        }
        __syncthreads();

        uint32_t aCur = sAraw + (uint32_t)(cur * ASZ) * 2 + a_off * 2;
        uint32_t bCur = sBraw + (uint32_t)(cur * ASZ) * 2 + b_off * 2;
        #pragma unroll
        for (int kk = 0; kk < 32; kk += 16) {
            uint32_t af[4][4], bq[2][4];
            #pragma unroll
            for (int mf = 0; mf < 4; mf++)
                ldsm_x4(af[mf], aCur + (uint32_t)(mf * 16 * SSTR + kk) * 2);
            #pragma unroll
            for (int nq = 0; nq < 2; nq++)
                ldsm_x4(bq[nq], bCur + (uint32_t)(nq * 16 * SSTR + kk) * 2);
            #pragma unroll
            for (int mf = 0; mf < 4; mf++)
                #pragma unroll
                for (int nf = 0; nf < 4; nf++)
                    mma16816(acc[mf][nf], af[mf], &bq[nf >> 1][(nf & 1) * 2]);
        }
        __syncthreads();
    }

    int ar = lane >> 2, ac = (lane & 3) * 2;
    if (mode == 0) {
        const float* xxb = xx + b * NP;
        float* st = (float*)sm;   // reuse pipeline smem for transpose staging
        #pragma unroll
        for (int mf = 0; mf < 4; mf++) {
            int r0g = row0 + wm + mf * 16 + ar;
            float xi0 = xxb[r0g], xi1 = xxb[r0g + 8];
            #pragma unroll
            for (int nf = 0; nf < 4; nf++) {
                int cg = col0 + wn + nf * 8 + ac;
                float* acc4 = acc[mf][nf];
                float xj0 = xxb[cg], xj1 = xxb[cg + 1];
                float2 v0, v1;
                v0.x = 2.f * acc4[0] - xi0 - xj0;
                v0.y = 2.f * acc4[1] - xi0 - xj1;
                v1.x = 2.f * acc4[2] - xi1 - xj0;
                v1.y = 2.f * acc4[3] - xi1 - xj1;
                *(float2*)(out + ((long long)b * NP + r0g) * ldo + cg) = v0;
                *(float2*)(out + ((long long)b * NP + r0g + 8) * ldo + cg) = v1;
                if (mirror) {
                    int lr0 = wm + mf * 16 + ar;
                    int lc0 = wn + nf * 8 + ac;
                    st[(lc0 + 0) * TSTR + lr0]     = v0.x;
                    st[(lc0 + 1) * TSTR + lr0]     = v0.y;
                    st[(lc0 + 0) * TSTR + lr0 + 8] = v1.x;
                    st[(lc0 + 1) * TSTR + lr0 + 8] = v1.y;
                }
            }
        }
        if (mirror) {
            __syncthreads();
            for (int e = tid; e < 128 * 32; e += 256) {
                int tr = e >> 5;
                int tc = (e & 31) * 4;
                float4 val = *(float4*)&st[tr * TSTR + tc];
                *(float4*)(out + ((long long)b * NP + col0 + tr) * ldo + row0 + tc) = val;
            }
        }
    } else {
        #pragma unroll
        for (int mf = 0; mf < 4; mf++) {
            int r0g = row0 + wm + mf * 16 + ar;
            #pragma unroll
            for (int nf = 0; nf < 4; nf++) {
                int cg = col0 + wn + nf * 8 + ac;
                float* acc4 = acc[mf][nf];
                *(__half2*)(outH + ((long long)b * NP + r0g) * ldo + cg) =
                    __floats2half2_rn(acc4[0], acc4[1]);
                *(__half2*)(outH + ((long long)b * NP + r0g + 8) * ldo + cg) =
                    __floats2half2_rn(acc4[2], acc4[3]);
            }
        }
    }
}

// =================== top-20: sorted top-4 queues + verify ===================
__global__ void topk_kernel(const float* __restrict__ dist, int* __restrict__ idx)
{
    int row = blockIdx.x * (blockDim.x >> 5) + (threadIdx.x >> 5);
    int lane = threadIdx.x & 31;
    if (row >= NB * NP) return;
    const float* d = dist + (size_t)row * NP;
    float v[32];
    #pragma unroll
    for (int s = 0; s < 32; s++) v[s] = d[s * 32 + lane];

    float m0 = -FLT_MAX, m1 = -FLT_MAX, m2 = -FLT_MAX, m3 = -FLT_MAX;
    int q0 = 0, q1 = 0, q2 = 0, q3 = 0;
    #pragma unroll
    for (int s = 0; s < 32; s++) {
        float x = v[s];
        if (x > m3) {
            if (x > m0)      { m3 = m2; q3 = q2; m2 = m1; q2 = q1; m1 = m0; q1 = q0; m0 = x; q0 = s; }
            else if (x > m1) { m3 = m2; q3 = q2; m2 = m1; q2 = q1; m1 = x;  q1 = s; }
            else if (x > m2) { m3 = m2; q3 = q2; m2 = x;  q2 = s; }
            else             { m3 = x;  q3 = s; }
        }
    }

    float thresh = 0.f;
    #pragma unroll
    for (int t = 0; t < KNN; t++) {
        float best = m0;
        #pragma unroll
        for (int off = 16; off; off >>= 1)
            best = fmaxf(best, __shfl_xor_sync(0xffffffffu, best, off));
        unsigned mask = __ballot_sync(0xffffffffu, m0 == best);
        int wl = __ffs(mask) - 1;
        int wq = __shfl_sync(0xffffffffu, q0, wl);
        if (lane == 0) idx[row * KNN + t] = wq * 32 + wl;
        if (lane == wl) { m0 = m1; q0 = q1; m1 = m2; q1 = q2; m2 = m3; q2 = q3; m3 = -FLT_MAX; }
        thresh = best;
    }

    int cnt = 0;
    #pragma unroll
    for (int s = 0; s < 32; s++) cnt += (v[s] > thresh) ? 1 : 0;
    cnt = __reduce_add_sync(0xffffffffu, cnt);
    if (cnt == 19) return;

    // rare fallback: exact iterative selection (element = s*32 + lane)
    for (int t = 0; t < KNN; t++) {
        float best = -FLT_MAX; int bs = 0;
        #pragma unroll
        for (int s = 0; s < 32; s++)
            if (v[s] > best) { best = v[s]; bs = s; }
        int bj = bs * 32 + lane;
        #pragma unroll
        for (int off = 16; off; off >>= 1) {
            float ov = __shfl_xor_sync(0xffffffffu, best, off);
            int oj = __shfl_xor_sync(0xffffffffu, bj, off);
            if (ov > best || (ov == best && oj < bj)) { best = ov; bj = oj; }
        }
        if (lane == 0) idx[row * KNN + t] = bj;
        if ((bj & 31) == lane) {
            int ks = bj >> 5;
            #pragma unroll
            for (int s = 0; s < 32; s++)
                if (s == ks) v[s] = -FLT_MAX;
        }
    }
}

// =================== edge aggregate (fp16 ab) ===================
__global__ void aggregate_kernel(const __half* __restrict__ ab, int O,
                                 const float* __restrict__ bias,
                                 const int* __restrict__ idx,
                                 float* __restrict__ out, int ldo, int ooff)
{
    int bi = blockIdx.x;
    int b = bi >> 10, i = bi & 1023;
    __shared__ int sj[KNN];
    if (threadIdx.x < KNN) sj[threadIdx.x] = idx[bi * KNN + threadIdx.x];
    __syncthreads();
    const __half* abb = ab + (size_t)b * NP * 2 * O;
    for (int o = threadIdx.x; o < O; o += blockDim.x) {
        float a = __half2float(abb[(size_t)i * 2 * O + o]) + bias[o];
        float acc = 0.f;
        #pragma unroll
        for (int k = 0; k < KNN; k++) {
            float val = a + __half2float(abb[(size_t)sj[k] * 2 * O + O + o]);
            acc += fmaxf(val, 0.2f * val);
        }
        out[((size_t)b * NP + i) * ldo + ooff + o] = acc * 0.05f;
    }
}

// =================== pooling + final linear ===================
__global__ void pool_kernel(const float* __restrict__ hf, float* __restrict__ pooled)
{
    int b = blockIdx.x;
    int o = blockIdx.y * blockDim.x + threadIdx.x;
    float s = 0.f;
    for (int i = 0; i < NP; i++) s += hf[((size_t)b * NP + i) * 512 + o];
    pooled[b * 512 + o] = s * (1.f / NP);
}

__global__ void final_kernel(const float* __restrict__ pooled, const float* __restrict__ We,
                             float* __restrict__ out)
{
    int b = blockIdx.x, e = threadIdx.x;
    const float* p = pooled + b * 512;
    const float* w = We + e * 512;
    float s = 0.f;
    for (int o = 0; o < 512; o++) s += p[o] * w[o];
    out[b * 256 + e] = s;
}

// =================== host side ===================
struct LayerCfg { int C, Cp, O, coff; const float *W, *g, *be, *m, *v; };

extern "C" void kernel_launch(void* const* d_in, const int* in_sizes, int n_in,
                              void* d_out, int out_size)
{
    const float* x  = (const float*)d_in[0];
    const float* We = (const float*)d_in[21];

    float *dist, *xx, *cat, *hf, *pooled, *bias4;
    __half* ab;
    int* idx;
    __nv_bfloat16 *hl, *whl4;
    cudaGetSymbolAddress((void**)&dist,   g_dist);
    cudaGetSymbolAddress((void**)&idx,    g_idx);
    cudaGetSymbolAddress((void**)&xx,     g_xx);
    cudaGetSymbolAddress((void**)&cat,    g_cat);
    cudaGetSymbolAddress((void**)&ab,     g_ab);
    cudaGetSymbolAddress((void**)&hf,     g_hf);
    cudaGetSymbolAddress((void**)&pooled, g_pooled);
    cudaGetSymbolAddress((void**)&bias4,  g_bias4);
    cudaGetSymbolAddress((void**)&hl,     g_hl);
    cudaGetSymbolAddress((void**)&whl4,   g_whl4);

    static cudaStream_t sB = nullptr;
    static cudaEvent_t evRoot, evS[4], evB[4];
    static bool attrSet = false;
    if (!sB) {
        cudaStreamCreateWithFlags(&sB, cudaStreamNonBlocking);
        cudaEventCreateWithFlags(&evRoot, cudaEventDisableTiming);
        for (int i = 0; i < 4; i++) {
            cudaEventCreateWithFlags(&evS[i], cudaEventDisableTiming);
            cudaEventCreateWithFlags(&evB[i], cudaEventDisableTiming);
        }
    }
    if (!attrSet) {
        cudaFuncSetAttribute(mma_gemm_kernel,
                             cudaFuncAttributeMaxDynamicSharedMemorySize, GEMM_SMEM);
        attrSet = true;
    }

    LayerCfg L[4] = {
        {  3,  32,  64,   0, (const float*)d_in[1],  (const float*)d_in[2],  (const float*)d_in[3],  (const float*)d_in[4],  (const float*)d_in[5]  },
        { 64,  64, 128,   0, (const float*)d_in[6],  (const float*)d_in[7],  (const float*)d_in[8],  (const float*)d_in[9],  (const float*)d_in[10] },
        {128, 128, 256,  64, (const float*)d_in[11], (const float*)d_in[12], (const float*)d_in[13], (const float*)d_in[14], (const float*)d_in[15] },
        {448, 448, 512,   0, (const float*)d_in[16], (const float*)d_in[17], (const float*)d_in[18], (const float*)d_in[19], (const float*)d_in[20] },
    };
    int ooffs[4] = {0, 64, 192, 0};

    cudaEventRecord(evRoot, 0);
    cudaStreamWaitEvent(sB, evRoot, 0);

    for (int i = 0; i < 4; i++) {
        wfoldsplit_kernel<<<2 * L[i].O, 128, 0, sB>>>(
            L[i].W, L[i].g, L[i].be, L[i].m, L[i].v, L[i].O, L[i].C, L[i].Cp,
            whl4 + (size_t)i * 1024 * HLMAX, bias4 + i * 512);
    }

    for (int i = 0; i < 4; i++) {
        int C = L[i].C, Cp = L[i].Cp, O = L[i].O, coff = L[i].coff;
        const float* hin = (i == 0) ? x : cat;
        int ld = (i == 0) ? 3 : 448;
        float* outbuf = (i == 3) ? hf : cat;
        int ldo = (i == 3) ? 512 : 448;

        split_kernel<<<NB * NP, 128>>>(hin, ld, coff, C, (long long)NP * ld, NP,
                                       hl, Cp, xx);
        cudaEventRecord(evS[i], 0);

        cudaStreamWaitEvent(sB, evS[i], 0);
        dim3 gw((2 * O) / 128, NP / 128, NB);
        mma_gemm_kernel<<<gw, 256, GEMM_SMEM, sB>>>(
            hl, whl4 + (size_t)i * 1024 * HLMAX, Cp,
            (long long)NP * 2 * Cp, 0, nullptr, 1, nullptr, ab, 2 * O);
        cudaEventRecord(evB[i], sB);

        // symmetric dist: 36 lower-triangle tiles per batch
        dim3 gd(36, 1, NB);
        mma_gemm_kernel<<<gd, 256, GEMM_SMEM>>>(
            hl, hl, Cp, (long long)NP * 2 * Cp, (long long)NP * 2 * Cp,
            xx, 0, dist, nullptr, NP);
        topk_kernel<<<NB * NP / 8, 256>>>(dist, idx);

        cudaStreamWaitEvent(0, evB[i], 0);
        int bt = O < 256 ? O : 256;
        aggregate_kernel<<<NB * NP, bt>>>(ab, O, bias4 + i * 512, idx,
                                          outbuf, ldo, ooffs[i]);
    }

    pool_kernel<<<dim3(NB, 2), 256>>>(hf, pooled);
    final_kernel<<<NB, 256>>>(pooled, We, (float*)d_out);
}

// round 17
// speedup vs baseline: 1.0844x; 1.0264x over previous
#include <cuda_runtime.h>
#include <cuda_bf16.h>
#include <math.h>
#include <float.h>
#include <stdint.h>

#define NB 8
#define NP 1024
#define KNN 20
#define HLMAX 896            // 2*448: [hi|lo] width for the largest layer

// ---------------- scratch (device globals; no allocation allowed) ----------------
__device__ __align__(16) float g_dist[NB * NP * NP];            // 32 MB
__device__ __align__(16) int   g_idx[NB * NP * KNN];
__device__ __align__(16) float g_xx[NB * NP];
__device__ __align__(16) float g_cat[NB * NP * 448];
__device__ __align__(16) float g_ab[NB * NP * 1024];
__device__ __align__(16) float g_hf[NB * NP * 512];
__device__ __align__(16) float g_pooled[NB * 512];
__device__ __align__(16) float g_bias4[4 * 512];
__device__ __align__(16) __nv_bfloat16 g_hl[NB * NP * HLMAX];    // features [hi|lo]
__device__ __align__(16) __nv_bfloat16 g_whl4[4][1024 * HLMAX];  // per-layer folded weights [hi|lo]

// =================== helpers ===================
__device__ __forceinline__ uint32_t smem_u32(const void* p) {
    uint32_t a;
    asm("{ .reg .u64 t; cvta.to.shared.u64 t, %1; cvt.u32.u64 %0, t; }" : "=r"(a) : "l"(p));
    return a;
}
__device__ __forceinline__ void cpa16(uint32_t s, const void* g) {
    asm volatile("cp.async.cg.shared.global [%0], [%1], 16;" :: "r"(s), "l"(g));
}
#define CP_COMMIT() asm volatile("cp.async.commit_group;")
#define CP_WAIT2()  asm volatile("cp.async.wait_group 2;")
#define CP_WAIT1()  asm volatile("cp.async.wait_group 1;")
#define CP_WAIT0()  asm volatile("cp.async.wait_group 0;")

__device__ __forceinline__ void ldsm_x4(uint32_t* r, uint32_t addr) {
    asm volatile("ldmatrix.sync.aligned.m8n8.x4.shared.b16 {%0,%1,%2,%3}, [%4];"
        : "=r"(r[0]), "=r"(r[1]), "=r"(r[2]), "=r"(r[3]) : "r"(addr));
}

// order-preserving float -> uint mapping (total order matches float <)
__device__ __forceinline__ uint32_t fmap(float f) {
    uint32_t u = __float_as_uint(f);
    return (u & 0x80000000u) ? ~u : (u | 0x80000000u);
}

// =================== feature split -> [hi(Cp) | lo(Cp)] + fused norms ===================
__global__ void split_kernel(const float* __restrict__ src, int ld, int coff, int C,
                             long long bstride, int rows_per_b,
                             __nv_bfloat16* __restrict__ hl, int Cp,
                             float* __restrict__ xxout)
{
    __shared__ float red[4];
    int r = blockIdx.x;
    int b = r / rows_per_b;
    int ri = r - b * rows_per_b;
    const float* p = src + (long long)b * bstride + (long long)ri * ld + coff;
    __nv_bfloat16* o = hl + (long long)r * 2 * Cp;
    __nv_bfloat16 z = __float2bfloat16(0.f);
    float ss = 0.f;
    for (int k = threadIdx.x; k < 2 * Cp; k += blockDim.x) {
        bool isHi = k < Cp;
        int c = isHi ? k : k - Cp;
        __nv_bfloat16 vv = z;
        if (c < C) {
            float x = p[c];
            if (isHi) ss += x * x;
            __nv_bfloat16 hi = __float2bfloat16(x);
            vv = isHi ? hi : __float2bfloat16(x - __bfloat162float(hi));
        }
        o[k] = vv;
    }
    int lane = threadIdx.x & 31, w = threadIdx.x >> 5;
    #pragma unroll
    for (int of = 16; of; of >>= 1) ss += __shfl_xor_sync(0xffffffffu, ss, of);
    if (!lane) red[w] = ss;
    __syncthreads();
    if (threadIdx.x == 0)
        xxout[r] = red[0] + red[1] + red[2] + red[3];
}

// =================== fold BN into weights -> [hi(Cp) | lo(Cp)] ===================
__global__ void wfoldsplit_kernel(const float* __restrict__ W, const float* __restrict__ g,
                                  const float* __restrict__ be, const float* __restrict__ m,
                                  const float* __restrict__ v, int O, int C, int Cp,
                                  __nv_bfloat16* __restrict__ whl,
                                  float* __restrict__ bias)
{
    int r = blockIdx.x;                 // 0 .. 2O-1
    bool isA = r < O;
    int o = isA ? r : r - O;
    float s = g[o] * rsqrtf(v[o] + 1e-5f);
    if (threadIdx.x == 0 && isA) bias[o] = be[o] - s * m[o];
    __nv_bfloat16* out = whl + (long long)r * 2 * Cp;
    __nv_bfloat16 z = __float2bfloat16(0.f);
    for (int k = threadIdx.x; k < 2 * Cp; k += blockDim.x) {
        bool isHi = k < Cp;
        int c = isHi ? k : k - Cp;
        __nv_bfloat16 vv = z;
        if (c < C) {
            float wc = W[o * 2 * C + c];
            float wd = W[o * 2 * C + C + c];
            float val = isA ? s * (wd - wc) : s * wc;
            __nv_bfloat16 hi = __float2bfloat16(val);
            vv = isHi ? hi : __float2bfloat16(val - __bfloat162float(hi));
        }
        out[k] = vv;
    }
}

// =================== mma.sync bf16 GEMM over virtual K = 3*Cp ===================
#define SSTR 56
#define ASZ  (128 * SSTR)
#define NSTAGE 3
#define GEMM_SMEM (NSTAGE * ASZ * 2 * 2)
#define TSTR 132            // transpose staging stride (floats)

__device__ __forceinline__ void mma16816(float* c, const uint32_t* a, const uint32_t* b)
{
    asm volatile(
        "mma.sync.aligned.m16n8k16.row.col.f32.bf16.bf16.f32 "
        "{%0,%1,%2,%3}, {%4,%5,%6,%7}, {%8,%9}, {%0,%1,%2,%3};"
        : "+f"(c[0]), "+f"(c[1]), "+f"(c[2]), "+f"(c[3])
        : "r"(a[0]), "r"(a[1]), "r"(a[2]), "r"(a[3]), "r"(b[0]), "r"(b[1]));
}

// mode 0: SYMMETRIC dist (gridDim.x=36 lower-triangle tiles; mirrors off-diag)
// mode 1: weight projection (grid x=2O/128, y=NP/128)
__global__ __launch_bounds__(256, 2) void mma_gemm_kernel(
    const __nv_bfloat16* __restrict__ A,
    const __nv_bfloat16* __restrict__ Bm,
    int Cp, long long bsA, long long bsB,
    const float* __restrict__ xx, int mode,
    float* __restrict__ out, int ldo)
{
    extern __shared__ __align__(16) __nv_bfloat16 sm[];
    __nv_bfloat16* As = sm;
    __nv_bfloat16* Bs = sm + NSTAGE * ASZ;

    int b = blockIdx.z;
    int row0, col0;
    bool mirror = false;
    if (mode == 0) {
        int t = blockIdx.x;            // 0..35 -> (bx<=by)
        int by = 0;
        while (t >= by + 1) { t -= by + 1; by++; }
        row0 = by * 128;
        col0 = t * 128;
        mirror = (t != by);
    } else {
        row0 = blockIdx.y * 128;
        col0 = blockIdx.x * 128;
    }

    int tid = threadIdx.x;
    int wid = tid >> 5, lane = tid & 31;
    int wm = (wid >> 2) * 64;
    int wn = (wid & 3) * 32;

    int ld2 = 2 * Cp;
    int nk = (3 * Cp) >> 5;

    const __nv_bfloat16* Ab = A + (long long)b * bsA;
    const __nv_bfloat16* Bb = Bm + (long long)b * bsB;

    int lr = tid >> 1;
    int lc = (tid & 1) * 16;

    uint32_t sAraw = smem_u32(As);
    uint32_t sBraw = smem_u32(Bs);
    uint32_t sA0 = sAraw + (uint32_t)(lr * SSTR + lc) * 2;
    uint32_t sB0 = sBraw + (uint32_t)(lr * SSTR + lc) * 2;
    const __nv_bfloat16* gA = Ab + (long long)(row0 + lr) * ld2 + lc;
    const __nv_bfloat16* gB = Bb + (long long)(col0 + lr) * ld2 + lc;

    uint32_t a_off = (uint32_t)((wm + (lane & 15)) * SSTR + (lane >> 4) * 8);
    uint32_t b_off = (uint32_t)((wn + (lane & 7) + ((lane >> 4) & 1) * 8) * SSTR
                                + ((lane >> 3) & 1) * 8);

    #pragma unroll
    for (int s = 0; s < NSTAGE - 1; s++) {
        if (s < nk) {
            int ka = s * 32;
            int koffA = (ka < 2 * Cp) ? ka : ka - 2 * Cp;
            int koffB = (ka < Cp) ? ka : ka - Cp;
            uint32_t da = sA0 + (uint32_t)(s * ASZ) * 2;
            uint32_t db = sB0 + (uint32_t)(s * ASZ) * 2;
            cpa16(da, gA + koffA); cpa16(da + 16, gA + koffA + 8);
            cpa16(db, gB + koffB); cpa16(db + 16, gB + koffB + 8);
            CP_COMMIT();
        }
    }

    float acc[4][4][4] = {};

    for (int kc = 0; kc < nk; kc++) {
        int cur = kc % NSTAGE;
        if (kc + 2 < nk) {
            int nxt = (kc + 2) % NSTAGE;
            int ka = (kc + 2) * 32;
            int koffA = (ka < 2 * Cp) ? ka : ka - 2 * Cp;
            int koffB = (ka < Cp) ? ka : ka - Cp;
            uint32_t da = sA0 + (uint32_t)(nxt * ASZ) * 2;
            uint32_t db = sB0 + (uint32_t)(nxt * ASZ) * 2;
            cpa16(da, gA + koffA); cpa16(da + 16, gA + koffA + 8);
            cpa16(db, gB + koffB); cpa16(db + 16, gB + koffB + 8);
            CP_COMMIT();
            CP_WAIT2();
        } else if (kc + 1 < nk) {
            CP_WAIT1();
        } else {
            CP_WAIT0();
        }
        __syncthreads();

        uint32_t aCur = sAraw + (uint32_t)(cur * ASZ) * 2 + a_off * 2;
        uint32_t bCur = sBraw + (uint32_t)(cur * ASZ) * 2 + b_off * 2;
        #pragma unroll
        for (int kk = 0; kk < 32; kk += 16) {
            uint32_t af[4][4], bq[2][4];
            #pragma unroll
            for (int mf = 0; mf < 4; mf++)
                ldsm_x4(af[mf], aCur + (uint32_t)(mf * 16 * SSTR + kk) * 2);
            #pragma unroll
            for (int nq = 0; nq < 2; nq++)
                ldsm_x4(bq[nq], bCur + (uint32_t)(nq * 16 * SSTR + kk) * 2);
            #pragma unroll
            for (int mf = 0; mf < 4; mf++)
                #pragma unroll
                for (int nf = 0; nf < 4; nf++)
                    mma16816(acc[mf][nf], af[mf], &bq[nf >> 1][(nf & 1) * 2]);
        }
        __syncthreads();
    }

    int ar = lane >> 2, ac = (lane & 3) * 2;
    if (mode == 0) {
        const float* xxb = xx + b * NP;
        float* st = (float*)sm;   // reuse pipeline smem for transpose staging
        #pragma unroll
        for (int mf = 0; mf < 4; mf++) {
            int r0g = row0 + wm + mf * 16 + ar;
            float xi0 = xxb[r0g], xi1 = xxb[r0g + 8];
            #pragma unroll
            for (int nf = 0; nf < 4; nf++) {
                int cg = col0 + wn + nf * 8 + ac;
                float* acc4 = acc[mf][nf];
                float xj0 = xxb[cg], xj1 = xxb[cg + 1];
                float2 v0, v1;
                v0.x = 2.f * acc4[0] - xi0 - xj0;
                v0.y = 2.f * acc4[1] - xi0 - xj1;
                v1.x = 2.f * acc4[2] - xi1 - xj0;
                v1.y = 2.f * acc4[3] - xi1 - xj1;
                *(float2*)(out + ((long long)b * NP + r0g) * ldo + cg) = v0;
                *(float2*)(out + ((long long)b * NP + r0g + 8) * ldo + cg) = v1;
                if (mirror) {
                    int lr0 = wm + mf * 16 + ar;
                    int lc0 = wn + nf * 8 + ac;
                    st[(lc0 + 0) * TSTR + lr0]     = v0.x;
                    st[(lc0 + 1) * TSTR + lr0]     = v0.y;
                    st[(lc0 + 0) * TSTR + lr0 + 8] = v1.x;
                    st[(lc0 + 1) * TSTR + lr0 + 8] = v1.y;
                }
            }
        }
        if (mirror) {
            __syncthreads();
            for (int e = tid; e < 128 * 32; e += 256) {
                int tr = e >> 5;
                int tc = (e & 31) * 4;
                float4 val = *(float4*)&st[tr * TSTR + tc];
                *(float4*)(out + ((long long)b * NP + col0 + tr) * ldo + row0 + tc) = val;
            }
        }
    } else {
        #pragma unroll
        for (int mf = 0; mf < 4; mf++) {
            int r0g = row0 + wm + mf * 16 + ar;
            #pragma unroll
            for (int nf = 0; nf < 4; nf++) {
                int cg = col0 + wn + nf * 8 + ac;
                float* acc4 = acc[mf][nf];
                float2 v0, v1;
                v0.x = acc4[0]; v0.y = acc4[1];
                v1.x = acc4[2]; v1.y = acc4[3];
                *(float2*)(out + ((long long)b * NP + r0g) * ldo + cg) = v0;
                *(float2*)(out + ((long long)b * NP + r0g + 8) * ldo + cg) = v1;
            }
        }
    }
}

// =================== top-20: REDUX-based selection on order-mapped uints ===================
// slot s of lane l holds element s*32 + l. All ordering done on fmap(v) uints
// (bit-exact same order as floats) so selected index sets are identical.
__global__ void topk_kernel(const float* __restrict__ dist, int* __restrict__ idx)
{
    int row = blockIdx.x * (blockDim.x >> 5) + (threadIdx.x >> 5);
    int lane = threadIdx.x & 31;
    if (row >= NB * NP) return;
    const float* d = dist + (size_t)row * NP;
    uint32_t u[32];
    #pragma unroll
    for (int s = 0; s < 32; s++) u[s] = fmap(d[s * 32 + lane]);

    // per-lane sorted top-4 queue (desc) on mapped uints
    uint32_t m0 = 0, m1 = 0, m2 = 0, m3 = 0;
    int q0 = 0, q1 = 0, q2 = 0, q3 = 0;
    #pragma unroll
    for (int s = 0; s < 32; s++) {
        uint32_t x = u[s];
        if (x > m3) {
            if (x > m0)      { m3 = m2; q3 = q2; m2 = m1; q2 = q1; m1 = m0; q1 = q0; m0 = x; q0 = s; }
            else if (x > m1) { m3 = m2; q3 = q2; m2 = m1; q2 = q1; m1 = x;  q1 = s; }
            else if (x > m2) { m3 = m2; q3 = q2; m2 = x;  q2 = s; }
            else             { m3 = x;  q3 = s; }
        }
    }

    uint32_t thresh = 0;
    #pragma unroll
    for (int t = 0; t < KNN; t++) {
        uint32_t best = __reduce_max_sync(0xffffffffu, m0);
        unsigned mask = __ballot_sync(0xffffffffu, m0 == best);
        int wl = __ffs(mask) - 1;
        int wq = __shfl_sync(0xffffffffu, q0, wl);
        if (lane == 0) idx[row * KNN + t] = wq * 32 + wl;
        if (lane == wl) { m0 = m1; q0 = q1; m1 = m2; q1 = q2; m2 = m3; q2 = q3; m3 = 0; }
        thresh = best;
    }

    int cnt = 0;
    #pragma unroll
    for (int s = 0; s < 32; s++) cnt += (u[s] > thresh) ? 1 : 0;
    cnt = __reduce_add_sync(0xffffffffu, cnt);
    if (cnt == 19) return;

    // rare fallback: exact iterative selection on mapped uints (element = s*32 + lane)
    for (int t = 0; t < KNN; t++) {
        uint32_t best = 0; int bs = 0;
        #pragma unroll
        for (int s = 0; s < 32; s++)
            if (u[s] > best) { best = u[s]; bs = s; }
        int bj = bs * 32 + lane;
        #pragma unroll
        for (int off = 16; off; off >>= 1) {
            uint32_t ov = __shfl_xor_sync(0xffffffffu, best, off);
            int oj = __shfl_xor_sync(0xffffffffu, bj, off);
            if (ov > best || (ov == best && oj < bj)) { best = ov; bj = oj; }
        }
        if (lane == 0) idx[row * KNN + t] = bj;
        if ((bj & 31) == lane) {
            int ks = bj >> 5;
            #pragma unroll
            for (int s = 0; s < 32; s++)
                if (s == ks) u[s] = 0;
        }
    }
}

// =================== edge aggregate (fp32 ab, R14-proven) ===================
__global__ void aggregate_kernel(const float* __restrict__ ab, int O,
                                 const float* __restrict__ bias,
                                 const int* __restrict__ idx,
                                 float* __restrict__ out, int ldo, int ooff)
{
    int bi = blockIdx.x;
    int b = bi >> 10, i = bi & 1023;
    __shared__ int sj[KNN];
    if (threadIdx.x < KNN) sj[threadIdx.x] = idx[bi * KNN + threadIdx.x];
    __syncthreads();
    const float* abb = ab + (size_t)b * NP * 2 * O;
    for (int o = threadIdx.x; o < O; o += blockDim.x) {
        float a = abb[(size_t)i * 2 * O + o] + bias[o];
        float acc = 0.f;
        #pragma unroll
        for (int k = 0; k < KNN; k++) {
            float val = a + abb[(size_t)sj[k] * 2 * O + O + o];
            acc += fmaxf(val, 0.2f * val);
        }
        out[((size_t)b * NP + i) * ldo + ooff + o] = acc * 0.05f;
    }
}

// =================== pooling + final linear ===================
__global__ void pool_kernel(const float* __restrict__ hf, float* __restrict__ pooled)
{
    int b = blockIdx.x;
    int o = blockIdx.y * blockDim.x + threadIdx.x;
    float s = 0.f;
    for (int i = 0; i < NP; i++) s += hf[((size_t)b * NP + i) * 512 + o];
    pooled[b * 512 + o] = s * (1.f / NP);
}

__global__ void final_kernel(const float* __restrict__ pooled, const float* __restrict__ We,
                             float* __restrict__ out)
{
    int b = blockIdx.x, e = threadIdx.x;
    const float* p = pooled + b * 512;
    const float* w = We + e * 512;
    float s = 0.f;
    for (int o = 0; o < 512; o++) s += p[o] * w[o];
    out[b * 256 + e] = s;
}

// =================== host side ===================
struct LayerCfg { int C, Cp, O, coff; const float *W, *g, *be, *m, *v; };

extern "C" void kernel_launch(void* const* d_in, const int* in_sizes, int n_in,
                              void* d_out, int out_size)
{
    const float* x  = (const float*)d_in[0];
    const float* We = (const float*)d_in[21];

    float *dist, *xx, *cat, *ab, *hf, *pooled, *bias4;
    int* idx;
    __nv_bfloat16 *hl, *whl4;
    cudaGetSymbolAddress((void**)&dist,   g_dist);
    cudaGetSymbolAddress((void**)&idx,    g_idx);
    cudaGetSymbolAddress((void**)&xx,     g_xx);
    cudaGetSymbolAddress((void**)&cat,    g_cat);
    cudaGetSymbolAddress((void**)&ab,     g_ab);
    cudaGetSymbolAddress((void**)&hf,     g_hf);
    cudaGetSymbolAddress((void**)&pooled, g_pooled);
    cudaGetSymbolAddress((void**)&bias4,  g_bias4);
    cudaGetSymbolAddress((void**)&hl,     g_hl);
    cudaGetSymbolAddress((void**)&whl4,   g_whl4);

    static cudaStream_t sB = nullptr;
    static cudaEvent_t evRoot, evS[4], evB[4];
    static bool attrSet = false;
    if (!sB) {
        cudaStreamCreateWithFlags(&sB, cudaStreamNonBlocking);
        cudaEventCreateWithFlags(&evRoot, cudaEventDisableTiming);
        for (int i = 0; i < 4; i++) {
            cudaEventCreateWithFlags(&evS[i], cudaEventDisableTiming);
            cudaEventCreateWithFlags(&evB[i], cudaEventDisableTiming);
        }
    }
    if (!attrSet) {
        cudaFuncSetAttribute(mma_gemm_kernel,
                             cudaFuncAttributeMaxDynamicSharedMemorySize, GEMM_SMEM);
        attrSet = true;
    }

    LayerCfg L[4] = {
        {  3,  32,  64,   0, (const float*)d_in[1],  (const float*)d_in[2],  (const float*)d_in[3],  (const float*)d_in[4],  (const float*)d_in[5]  },
        { 64,  64, 128,   0, (const float*)d_in[6],  (const float*)d_in[7],  (const float*)d_in[8],  (const float*)d_in[9],  (const float*)d_in[10] },
        {128, 128, 256,  64, (const float*)d_in[11], (const float*)d_in[12], (const float*)d_in[13], (const float*)d_in[14], (const float*)d_in[15] },
        {448, 448, 512,   0, (const float*)d_in[16], (const float*)d_in[17], (const float*)d_in[18], (const float*)d_in[19], (const float*)d_in[20] },
    };
    int ooffs[4] = {0, 64, 192, 0};

    cudaEventRecord(evRoot, 0);
    cudaStreamWaitEvent(sB, evRoot, 0);

    for (int i = 0; i < 4; i++) {
        wfoldsplit_kernel<<<2 * L[i].O, 128, 0, sB>>>(
            L[i].W, L[i].g, L[i].be, L[i].m, L[i].v, L[i].O, L[i].C, L[i].Cp,
            whl4 + (size_t)i * 1024 * HLMAX, bias4 + i * 512);
    }

    for (int i = 0; i < 4; i++) {
        int C = L[i].C, Cp = L[i].Cp, O = L[i].O, coff = L[i].coff;
        const float* hin = (i == 0) ? x : cat;
        int ld = (i == 0) ? 3 : 448;
        float* outbuf = (i == 3) ? hf : cat;
        int ldo = (i == 3) ? 512 : 448;

        split_kernel<<<NB * NP, 128>>>(hin, ld, coff, C, (long long)NP * ld, NP,
                                       hl, Cp, xx);
        cudaEventRecord(evS[i], 0);

        cudaStreamWaitEvent(sB, evS[i], 0);
        dim3 gw((2 * O) / 128, NP / 128, NB);
        mma_gemm_kernel<<<gw, 256, GEMM_SMEM, sB>>>(
            hl, whl4 + (size_t)i * 1024 * HLMAX, Cp,
            (long long)NP * 2 * Cp, 0, nullptr, 1, ab, 2 * O);
        cudaEventRecord(evB[i], sB);

        // symmetric dist: 36 lower-triangle tiles per batch
        dim3 gd(36, 1, NB);
        mma_gemm_kernel<<<gd, 256, GEMM_SMEM>>>(
            hl, hl, Cp, (long long)NP * 2 * Cp, (long long)NP * 2 * Cp,
            xx, 0, dist, NP);
        topk_kernel<<<NB * NP / 8, 256>>>(dist, idx);

        cudaStreamWaitEvent(0, evB[i], 0);
        int bt = O < 256 ? O : 256;
        aggregate_kernel<<<NB * NP, bt>>>(ab, O, bias4 + i * 512, idx,
                                          outbuf, ldo, ooffs[i]);
    }

    pool_kernel<<<dim3(NB, 2), 256>>>(hf, pooled);
    final_kernel<<<NB, 256>>>(pooled, We, (float*)d_out);
}